// round 1
// baseline (speedup 1.0000x reference)
#include <cuda_runtime.h>
#include <math_constants.h>

#define E_ 1024
#define W_ 1024
#define B_ 4
#define H_ 16
#define D_ 64
#define BH_ 64   // B_*H_

// Scratch (allocation-free: __device__ globals)
__device__ float g_qkv[3ull * B_ * E_ * W_];        // [p][b][e][w]; p: 0=K, 1=Q, 2=V   (48 MB)
__device__ float g_scores[(size_t)BH_ * W_ * W_];   // [bh][q][k]; becomes attn after softmax (256 MB)
__device__ float g_attn_out[(size_t)B_ * E_ * W_];  // [b][e][w] (16 MB)

// ---------------------------------------------------------------------------
// 128x128 tile SGEMM body, NN: A row-major [M,K], B row-major [K,N]
// 256 threads, 8x8 microtile per thread (split 4+4 rows/cols for bank-friendly LDS.128)
// ---------------------------------------------------------------------------
__device__ __forceinline__ void gemm128_nn_body(
    const float* __restrict__ A, int lda,
    const float* __restrict__ Bm, int ldb,
    float* __restrict__ C, int ldc,
    int Kdim, const float* __restrict__ bias)
{
    __shared__ float As[8][128];   // [k][m]
    __shared__ float Bs[8][128];   // [k][n]

    const int tid = threadIdx.x;
    const int tx  = tid & 15;      // n direction
    const int ty  = tid >> 4;      // m direction
    const int m0  = blockIdx.y * 128;
    const int n0  = blockIdx.x * 128;

    float acc[8][8];
#pragma unroll
    for (int i = 0; i < 8; i++)
#pragma unroll
        for (int j = 0; j < 8; j++) acc[i][j] = 0.f;

    const int arow = tid >> 1;          // 0..127
    const int acol = (tid & 1) * 4;     // 0 or 4
    const int brow = tid >> 5;          // 0..7
    const int bcol = (tid & 31) * 4;    // 0..124

    const float* Ap = A  + (size_t)(m0 + arow) * lda + acol;
    const float* Bp = Bm + (size_t)brow * ldb + n0 + bcol;

    for (int kt = 0; kt < Kdim; kt += 8) {
        float4 av = *(const float4*)(Ap + kt);
        float4 bv = *(const float4*)(Bp + (size_t)kt * ldb);
        As[acol + 0][arow] = av.x;
        As[acol + 1][arow] = av.y;
        As[acol + 2][arow] = av.z;
        As[acol + 3][arow] = av.w;
        *(float4*)(&Bs[brow][bcol]) = bv;
        __syncthreads();
#pragma unroll
        for (int kk = 0; kk < 8; kk++) {
            float4 a0 = *(const float4*)(&As[kk][ty * 4]);
            float4 a1 = *(const float4*)(&As[kk][64 + ty * 4]);
            float4 b0 = *(const float4*)(&Bs[kk][tx * 4]);
            float4 b1 = *(const float4*)(&Bs[kk][64 + tx * 4]);
            float a[8]  = {a0.x, a0.y, a0.z, a0.w, a1.x, a1.y, a1.z, a1.w};
            float bb[8] = {b0.x, b0.y, b0.z, b0.w, b1.x, b1.y, b1.z, b1.w};
#pragma unroll
            for (int i = 0; i < 8; i++)
#pragma unroll
                for (int j = 0; j < 8; j++) acc[i][j] += a[i] * bb[j];
        }
        __syncthreads();
    }

#pragma unroll
    for (int ih = 0; ih < 2; ih++)
#pragma unroll
        for (int i = 0; i < 4; i++) {
            int row = m0 + ih * 64 + ty * 4 + i;
            float bval = bias ? bias[row] : 0.f;
#pragma unroll
            for (int jh = 0; jh < 2; jh++) {
                float4 v;
                v.x = acc[ih * 4 + i][jh * 4 + 0] + bval;
                v.y = acc[ih * 4 + i][jh * 4 + 1] + bval;
                v.z = acc[ih * 4 + i][jh * 4 + 2] + bval;
                v.w = acc[ih * 4 + i][jh * 4 + 3] + bval;
                *(float4*)(&C[(size_t)row * ldc + n0 + jh * 64 + tx * 4]) = v;
            }
        }
}

// ---------------------------------------------------------------------------
// 128x128 tile SGEMM body, TN: C[m,n] = sum_k A[k,m] * B[k,n]
// (both operands K-major -> no transpose on load)
// ---------------------------------------------------------------------------
__device__ __forceinline__ void gemm128_tn_body(
    const float* __restrict__ A, int lda,   // [Kdim][M]
    const float* __restrict__ Bm, int ldb,  // [Kdim][N]
    float* __restrict__ C, int ldc,
    int Kdim)
{
    __shared__ float As[8][128];
    __shared__ float Bs[8][128];

    const int tid = threadIdx.x;
    const int tx  = tid & 15;
    const int ty  = tid >> 4;
    const int m0  = blockIdx.y * 128;
    const int n0  = blockIdx.x * 128;

    float acc[8][8];
#pragma unroll
    for (int i = 0; i < 8; i++)
#pragma unroll
        for (int j = 0; j < 8; j++) acc[i][j] = 0.f;

    const int row  = tid >> 5;          // 0..7
    const int col4 = (tid & 31) * 4;    // 0..124

    for (int kt = 0; kt < Kdim; kt += 8) {
        float4 av = *(const float4*)(A  + (size_t)(kt + row) * lda + m0 + col4);
        float4 bv = *(const float4*)(Bm + (size_t)(kt + row) * ldb + n0 + col4);
        *(float4*)(&As[row][col4]) = av;
        *(float4*)(&Bs[row][col4]) = bv;
        __syncthreads();
#pragma unroll
        for (int kk = 0; kk < 8; kk++) {
            float4 a0 = *(const float4*)(&As[kk][ty * 4]);
            float4 a1 = *(const float4*)(&As[kk][64 + ty * 4]);
            float4 b0 = *(const float4*)(&Bs[kk][tx * 4]);
            float4 b1 = *(const float4*)(&Bs[kk][64 + tx * 4]);
            float a[8]  = {a0.x, a0.y, a0.z, a0.w, a1.x, a1.y, a1.z, a1.w};
            float bb[8] = {b0.x, b0.y, b0.z, b0.w, b1.x, b1.y, b1.z, b1.w};
#pragma unroll
            for (int i = 0; i < 8; i++)
#pragma unroll
                for (int j = 0; j < 8; j++) acc[i][j] += a[i] * bb[j];
        }
        __syncthreads();
    }

#pragma unroll
    for (int ih = 0; ih < 2; ih++)
#pragma unroll
        for (int i = 0; i < 4; i++) {
            int r = m0 + ih * 64 + ty * 4 + i;
#pragma unroll
            for (int jh = 0; jh < 2; jh++) {
                float4 v;
                v.x = acc[ih * 4 + i][jh * 4 + 0];
                v.y = acc[ih * 4 + i][jh * 4 + 1];
                v.z = acc[ih * 4 + i][jh * 4 + 2];
                v.w = acc[ih * 4 + i][jh * 4 + 3];
                *(float4*)(&C[(size_t)r * ldc + n0 + jh * 64 + tx * 4]) = v;
            }
        }
}

// ---------------------------------------------------------------------------
// Kernel 1: projections.  z = p*4 + b;  g_qkv[p][b] = L_p @ x[p][b]
//   p=0: K = L_K @ x[0];  p=1: Q = L_Q @ x[1];  p=2: V = L_V @ x[2]
// ---------------------------------------------------------------------------
__global__ __launch_bounds__(256) void k_proj(
    const float* __restrict__ x,
    const float* __restrict__ LQ,
    const float* __restrict__ LK,
    const float* __restrict__ LV)
{
    int z = blockIdx.z;
    int p = z >> 2;
    const float* A  = (p == 0) ? LK : (p == 1) ? LQ : LV;
    const float* Bm = x + (size_t)z * E_ * W_;
    float*       C  = g_qkv + (size_t)z * E_ * W_;
    gemm128_nn_body(A, E_, Bm, W_, C, W_, E_, nullptr);
}

// ---------------------------------------------------------------------------
// Kernel 2: scores. S[bh][q][k] = sum_d Q[d,q] * K[d,k]. Skip fully-masked tiles.
// ---------------------------------------------------------------------------
__global__ __launch_bounds__(256) void k_scores()
{
    int z = blockIdx.z;            // bh
    int m0 = blockIdx.y * 128;     // q tile
    int n0 = blockIdx.x * 128;     // k tile
    if (m0 > n0 + 127) return;     // whole tile has q > k -> masked, never read
    int b = z >> 4, h = z & 15;
    const float* Aq = g_qkv + (size_t)(4 + b) * E_ * W_ + (size_t)h * D_ * W_; // Q
    const float* Bk = g_qkv + (size_t)(0 + b) * E_ * W_ + (size_t)h * D_ * W_; // K
    float* Sp = g_scores + (size_t)z * W_ * W_;
    gemm128_tn_body(Aq, W_, Bk, W_, Sp, W_, D_);
}

// ---------------------------------------------------------------------------
// Kernel 3: column-wise masked softmax over q (axis=-2), scaled by 1/32.
// Block: 32 columns x 8 q-lanes. Writes attn in-place (zeros for q > k).
// ---------------------------------------------------------------------------
__global__ __launch_bounds__(256) void k_softmax()
{
    int z  = blockIdx.y;
    int k0 = blockIdx.x * 32;
    int tx = threadIdx.x & 31;
    int ty = threadIdx.x >> 5;
    int k  = k0 + tx;
    float* Sp = g_scores + (size_t)z * W_ * W_;

    float m = -CUDART_INF_F, l = 0.f;
    for (int q = ty; q <= k; q += 8) {
        float s = Sp[(size_t)q * W_ + k];
        if (s > m) { l *= __expf(m - s); m = s; }
        l += __expf(s - m);
    }

    __shared__ float ms[8][32], ls[8][32];
    ms[ty][tx] = m; ls[ty][tx] = l;
    __syncthreads();

    float M2 = ms[0][tx], L2 = ls[0][tx];   // ty=0 always has q=0 valid -> finite
#pragma unroll
    for (int i = 1; i < 8; i++) {
        float mi = ms[i][tx], li = ls[i][tx];
        float nm = fmaxf(M2, mi);
        L2 = L2 * __expf(M2 - nm) + li * __expf(mi - nm);
        M2 = nm;
    }
    float inv = 1.0f / (L2 * 32.0f);   // fold 1/sqrt(E) = 1/32

    for (int q = ty; q < W_; q += 8) {
        float v = 0.f;
        if (q <= k) v = __expf(Sp[(size_t)q * W_ + k] - M2) * inv;
        Sp[(size_t)q * W_ + k] = v;
    }
}

// ---------------------------------------------------------------------------
// Kernel 4: O[d,k] = sum_q V[d,q] * attn[q,k].  M=64, tile 64x128, BK=16.
// Causal: attn[q,k]=0 for q>k, so bound the q loop at n0+128.
// ---------------------------------------------------------------------------
__global__ __launch_bounds__(256) void k_attnv()
{
    __shared__ float As[16][64];    // [q][d]
    __shared__ float Bs[16][128];   // [q][k]

    int z = blockIdx.y, b = z >> 4, h = z & 15;
    int n0 = blockIdx.x * 128;
    const float* V = g_qkv + (size_t)(8 + b) * E_ * W_ + (size_t)h * D_ * W_;
    const float* P = g_scores + (size_t)z * W_ * W_;
    float* O = g_attn_out + (size_t)b * E_ * W_ + (size_t)h * D_ * W_;

    int tid = threadIdx.x;
    int tx = tid & 15, ty = tid >> 4;

    float acc[4][8];
#pragma unroll
    for (int i = 0; i < 4; i++)
#pragma unroll
        for (int j = 0; j < 8; j++) acc[i][j] = 0.f;

    const int arow = tid >> 2;        // 0..63 (d)
    const int acol = (tid & 3) * 4;   // 0..12 (q offset within 16)
    const int brow = tid >> 4;        // 0..15 (q)
    const int bcol = (tid & 15) * 4;  // 0..60

    const int qmax = n0 + 128;
    for (int kt = 0; kt < qmax; kt += 16) {
        float4 av = *(const float4*)(V + (size_t)arow * W_ + kt + acol);
        As[acol + 0][arow] = av.x;
        As[acol + 1][arow] = av.y;
        As[acol + 2][arow] = av.z;
        As[acol + 3][arow] = av.w;
        const float* Prow = P + (size_t)(kt + brow) * W_ + n0;
        *(float4*)(&Bs[brow][bcol])      = *(const float4*)(Prow + bcol);
        *(float4*)(&Bs[brow][bcol + 64]) = *(const float4*)(Prow + bcol + 64);
        __syncthreads();
#pragma unroll
        for (int kk = 0; kk < 16; kk++) {
            float4 a  = *(const float4*)(&As[kk][ty * 4]);
            float4 b0 = *(const float4*)(&Bs[kk][tx * 4]);
            float4 b1 = *(const float4*)(&Bs[kk][64 + tx * 4]);
            float aa[4] = {a.x, a.y, a.z, a.w};
            float bb[8] = {b0.x, b0.y, b0.z, b0.w, b1.x, b1.y, b1.z, b1.w};
#pragma unroll
            for (int i = 0; i < 4; i++)
#pragma unroll
                for (int j = 0; j < 8; j++) acc[i][j] += aa[i] * bb[j];
        }
        __syncthreads();
    }

#pragma unroll
    for (int i = 0; i < 4; i++) {
        int row = ty * 4 + i;
#pragma unroll
        for (int jh = 0; jh < 2; jh++) {
            float4 v;
            v.x = acc[i][jh * 4 + 0];
            v.y = acc[i][jh * 4 + 1];
            v.z = acc[i][jh * 4 + 2];
            v.w = acc[i][jh * 4 + 3];
            *(float4*)(&O[(size_t)row * W_ + n0 + jh * 64 + tx * 4]) = v;
        }
    }
}

// ---------------------------------------------------------------------------
// Kernel 5: y[b] = M @ O[b] + bias
// ---------------------------------------------------------------------------
__global__ __launch_bounds__(256) void k_final(
    const float* __restrict__ Mw,
    const float* __restrict__ bias,
    float* __restrict__ out)
{
    int b = blockIdx.z;
    gemm128_nn_body(Mw, E_, g_attn_out + (size_t)b * E_ * W_, W_,
                    out + (size_t)b * E_ * W_, W_, E_, bias);
}

// ---------------------------------------------------------------------------
extern "C" void kernel_launch(void* const* d_in, const int* in_sizes, int n_in,
                              void* d_out, int out_size)
{
    const float* x  = (const float*)d_in[0];
    const float* LQ = (const float*)d_in[1];
    const float* LK = (const float*)d_in[2];
    const float* LV = (const float*)d_in[3];
    const float* Mw = (const float*)d_in[4];
    const float* bv = (const float*)d_in[5];
    float* out = (float*)d_out;

    dim3 blk(256);
    k_proj   <<<dim3(8, 8, 12), blk>>>(x, LQ, LK, LV);
    k_scores <<<dim3(8, 8, 64), blk>>>();
    k_softmax<<<dim3(32, 64),   blk>>>();
    k_attnv  <<<dim3(8, 64),    blk>>>();
    k_final  <<<dim3(8, 8, 4),  blk>>>(Mw, bv, out);
}

// round 2
// speedup vs baseline: 1.1303x; 1.1303x over previous
#include <cuda_runtime.h>
#include <math_constants.h>

#define E_ 1024
#define W_ 1024
#define B_ 4
#define H_ 16
#define D_ 64
#define BH_ 64   // B_*H_

// Scratch (allocation-free: __device__ globals)
__device__ float g_qkv[3ull * B_ * E_ * W_];        // [p][b][e][w]; p: 0=K, 1=Q, 2=V
__device__ float g_scores[(size_t)BH_ * W_ * W_];   // [bh][q][k]; becomes unnormalized P after softmax
__device__ float g_attn_out[(size_t)B_ * E_ * W_];  // [b][e][w]
__device__ float g_inv[BH_ * W_];                   // per-column 1/(32*l)

// ---------------------------------------------------------------------------
// 128x128 SGEMM body, NN, BK=16, double-buffered smem, 256 threads, 8x8 micro
// A row-major [M,K], B row-major [K,N]
// ---------------------------------------------------------------------------
__device__ __forceinline__ void gemm_nn_db(
    const float* __restrict__ A, int lda,
    const float* __restrict__ Bm, int ldb,
    float* __restrict__ C, int ldc,
    int Kdim, const float* __restrict__ bias)
{
    __shared__ float As[2][16][128];   // [buf][k][m]
    __shared__ float Bs[2][16][128];   // [buf][k][n]

    const int tid = threadIdx.x;
    const int tx  = tid & 15;
    const int ty  = tid >> 4;
    const int m0  = blockIdx.y * 128;
    const int n0  = blockIdx.x * 128;

    const int arow = tid >> 1;          // 0..127 (m)
    const int acol = (tid & 1) * 8;     // 0 or 8 (k offset)
    const int brow = tid >> 4;          // 0..15 (k)
    const int bcol = (tid & 15) * 4;    // 0..60 (n offset)

    const float* Ap = A  + (size_t)(m0 + arow) * lda + acol;
    const float* Bp = Bm + (size_t)brow * ldb + n0 + bcol;

    float acc[8][8];
#pragma unroll
    for (int i = 0; i < 8; i++)
#pragma unroll
        for (int j = 0; j < 8; j++) acc[i][j] = 0.f;

    // preload stage 0
    {
        float4 a0 = *(const float4*)(Ap);
        float4 a1 = *(const float4*)(Ap + 4);
        float4 b0 = *(const float4*)(Bp);
        float4 b1 = *(const float4*)(Bp + 64);
        As[0][acol + 0][arow] = a0.x;
        As[0][acol + 1][arow] = a0.y;
        As[0][acol + 2][arow] = a0.z;
        As[0][acol + 3][arow] = a0.w;
        As[0][acol + 4][arow] = a1.x;
        As[0][acol + 5][arow] = a1.y;
        As[0][acol + 6][arow] = a1.z;
        As[0][acol + 7][arow] = a1.w;
        *(float4*)(&Bs[0][brow][bcol])      = b0;
        *(float4*)(&Bs[0][brow][bcol + 64]) = b1;
    }
    __syncthreads();

    int buf = 0;
    for (int kt = 16; kt <= Kdim; kt += 16) {
        const bool has = (kt < Kdim);
        float4 a0 = {0,0,0,0}, a1 = {0,0,0,0}, b0 = {0,0,0,0}, b1 = {0,0,0,0};
        if (has) {
            a0 = *(const float4*)(Ap + kt);
            a1 = *(const float4*)(Ap + kt + 4);
            b0 = *(const float4*)(Bp + (size_t)kt * ldb);
            b1 = *(const float4*)(Bp + (size_t)kt * ldb + 64);
        }
#pragma unroll
        for (int kk = 0; kk < 16; kk++) {
            float4 A0 = *(const float4*)(&As[buf][kk][ty * 4]);
            float4 A1 = *(const float4*)(&As[buf][kk][64 + ty * 4]);
            float4 B0 = *(const float4*)(&Bs[buf][kk][tx * 4]);
            float4 B1 = *(const float4*)(&Bs[buf][kk][64 + tx * 4]);
            float a[8]  = {A0.x, A0.y, A0.z, A0.w, A1.x, A1.y, A1.z, A1.w};
            float bb[8] = {B0.x, B0.y, B0.z, B0.w, B1.x, B1.y, B1.z, B1.w};
#pragma unroll
            for (int i = 0; i < 8; i++)
#pragma unroll
                for (int j = 0; j < 8; j++) acc[i][j] += a[i] * bb[j];
        }
        if (has) {
            int nb = buf ^ 1;
            As[nb][acol + 0][arow] = a0.x;
            As[nb][acol + 1][arow] = a0.y;
            As[nb][acol + 2][arow] = a0.z;
            As[nb][acol + 3][arow] = a0.w;
            As[nb][acol + 4][arow] = a1.x;
            As[nb][acol + 5][arow] = a1.y;
            As[nb][acol + 6][arow] = a1.z;
            As[nb][acol + 7][arow] = a1.w;
            *(float4*)(&Bs[nb][brow][bcol])      = b0;
            *(float4*)(&Bs[nb][brow][bcol + 64]) = b1;
        }
        __syncthreads();
        buf ^= 1;
    }

#pragma unroll
    for (int ih = 0; ih < 2; ih++)
#pragma unroll
        for (int i = 0; i < 4; i++) {
            int row = m0 + ih * 64 + ty * 4 + i;
            float bval = bias ? bias[row] : 0.f;
#pragma unroll
            for (int jh = 0; jh < 2; jh++) {
                float4 v;
                v.x = acc[ih * 4 + i][jh * 4 + 0] + bval;
                v.y = acc[ih * 4 + i][jh * 4 + 1] + bval;
                v.z = acc[ih * 4 + i][jh * 4 + 2] + bval;
                v.w = acc[ih * 4 + i][jh * 4 + 3] + bval;
                *(float4*)(&C[(size_t)row * ldc + n0 + jh * 64 + tx * 4]) = v;
            }
        }
}

// ---------------------------------------------------------------------------
// 128x128 SGEMM body, TN (both K-major), BK=16, double-buffered
// C[m,n] = sum_k A[k,m] * B[k,n]
// ---------------------------------------------------------------------------
__device__ __forceinline__ void gemm_tn_db(
    const float* __restrict__ A, int lda,   // [Kdim][M]
    const float* __restrict__ Bm, int ldb,  // [Kdim][N]
    float* __restrict__ C, int ldc, int Kdim)
{
    __shared__ float As[2][16][128];
    __shared__ float Bs[2][16][128];

    const int tid = threadIdx.x;
    const int tx  = tid & 15;
    const int ty  = tid >> 4;
    const int m0  = blockIdx.y * 128;
    const int n0  = blockIdx.x * 128;

    const int row  = tid >> 4;          // 0..15 (k)
    const int col4 = (tid & 15) * 4;    // 0..60

    const float* Ap = A  + (size_t)row * lda + m0 + col4;
    const float* Bp = Bm + (size_t)row * ldb + n0 + col4;

    float acc[8][8];
#pragma unroll
    for (int i = 0; i < 8; i++)
#pragma unroll
        for (int j = 0; j < 8; j++) acc[i][j] = 0.f;

    {
        *(float4*)(&As[0][row][col4])      = *(const float4*)(Ap);
        *(float4*)(&As[0][row][col4 + 64]) = *(const float4*)(Ap + 64);
        *(float4*)(&Bs[0][row][col4])      = *(const float4*)(Bp);
        *(float4*)(&Bs[0][row][col4 + 64]) = *(const float4*)(Bp + 64);
    }
    __syncthreads();

    int buf = 0;
    for (int kt = 16; kt <= Kdim; kt += 16) {
        const bool has = (kt < Kdim);
        float4 a0 = {0,0,0,0}, a1 = {0,0,0,0}, b0 = {0,0,0,0}, b1 = {0,0,0,0};
        if (has) {
            a0 = *(const float4*)(Ap + (size_t)kt * lda);
            a1 = *(const float4*)(Ap + (size_t)kt * lda + 64);
            b0 = *(const float4*)(Bp + (size_t)kt * ldb);
            b1 = *(const float4*)(Bp + (size_t)kt * ldb + 64);
        }
#pragma unroll
        for (int kk = 0; kk < 16; kk++) {
            float4 A0 = *(const float4*)(&As[buf][kk][ty * 4]);
            float4 A1 = *(const float4*)(&As[buf][kk][64 + ty * 4]);
            float4 B0 = *(const float4*)(&Bs[buf][kk][tx * 4]);
            float4 B1 = *(const float4*)(&Bs[buf][kk][64 + tx * 4]);
            float a[8]  = {A0.x, A0.y, A0.z, A0.w, A1.x, A1.y, A1.z, A1.w};
            float bb[8] = {B0.x, B0.y, B0.z, B0.w, B1.x, B1.y, B1.z, B1.w};
#pragma unroll
            for (int i = 0; i < 8; i++)
#pragma unroll
                for (int j = 0; j < 8; j++) acc[i][j] += a[i] * bb[j];
        }
        if (has) {
            int nb = buf ^ 1;
            *(float4*)(&As[nb][row][col4])      = a0;
            *(float4*)(&As[nb][row][col4 + 64]) = a1;
            *(float4*)(&Bs[nb][row][col4])      = b0;
            *(float4*)(&Bs[nb][row][col4 + 64]) = b1;
        }
        __syncthreads();
        buf ^= 1;
    }

#pragma unroll
    for (int ih = 0; ih < 2; ih++)
#pragma unroll
        for (int i = 0; i < 4; i++) {
            int r = m0 + ih * 64 + ty * 4 + i;
#pragma unroll
            for (int jh = 0; jh < 2; jh++) {
                float4 v;
                v.x = acc[ih * 4 + i][jh * 4 + 0];
                v.y = acc[ih * 4 + i][jh * 4 + 1];
                v.z = acc[ih * 4 + i][jh * 4 + 2];
                v.w = acc[ih * 4 + i][jh * 4 + 3];
                *(float4*)(&C[(size_t)r * ldc + n0 + jh * 64 + tx * 4]) = v;
            }
        }
}

// ---------------------------------------------------------------------------
// Kernel 1: projections. z = p*4 + b; g_qkv[p][b] = L_p @ x[p][b]
// ---------------------------------------------------------------------------
__global__ __launch_bounds__(256, 2) void k_proj(
    const float* __restrict__ x,
    const float* __restrict__ LQ,
    const float* __restrict__ LK,
    const float* __restrict__ LV)
{
    int z = blockIdx.z;
    int p = z >> 2;
    const float* A  = (p == 0) ? LK : (p == 1) ? LQ : LV;
    const float* Bm = x + (size_t)z * E_ * W_;
    float*       C  = g_qkv + (size_t)z * E_ * W_;
    gemm_nn_db(A, E_, Bm, W_, C, W_, E_, nullptr);
}

// ---------------------------------------------------------------------------
// Kernel 2: scores. S[bh][q][k] = sum_d Q[d,q] * K[d,k]. Skip fully-masked tiles.
// ---------------------------------------------------------------------------
__global__ __launch_bounds__(256, 2) void k_scores()
{
    int z = blockIdx.z;            // bh
    int m0 = blockIdx.y * 128;     // q tile
    int n0 = blockIdx.x * 128;     // k tile
    if (m0 > n0 + 127) return;     // fully masked tile (q > k everywhere)
    int b = z >> 4, h = z & 15;
    const float* Aq = g_qkv + (size_t)(4 + b) * E_ * W_ + (size_t)h * D_ * W_; // Q
    const float* Bk = g_qkv + (size_t)(0 + b) * E_ * W_ + (size_t)h * D_ * W_; // K
    float* Sp = g_scores + (size_t)z * W_ * W_;
    gemm_tn_db(Aq, W_, Bk, W_, Sp, W_, D_);
}

// ---------------------------------------------------------------------------
// Kernel 3: column softmax over q (axis=-2), causal q<=k. Two passes:
//  pass1 max (no exp), pass2 exp+sum, store UNNORMALIZED P (0 for q>k),
//  write per-column 1/(32*l) into g_inv (applied later in k_attnv).
// ---------------------------------------------------------------------------
__global__ __launch_bounds__(256) void k_softmax()
{
    int z  = blockIdx.y;
    int k0 = blockIdx.x * 32;
    int tx = threadIdx.x & 31;
    int ty = threadIdx.x >> 5;
    int k  = k0 + tx;
    float* Sp = g_scores + (size_t)z * W_ * W_;

    __shared__ float red[8][32];

    float m = -CUDART_INF_F;
    for (int q = ty; q <= k; q += 8)
        m = fmaxf(m, Sp[(size_t)q * W_ + k]);
    red[ty][tx] = m;
    __syncthreads();

    float M2 = red[0][tx];
#pragma unroll
    for (int i = 1; i < 8; i++) M2 = fmaxf(M2, red[i][tx]);
    __syncthreads();

    float l = 0.f;
    for (int q = ty; q < W_; q += 8) {
        float v = 0.f;
        if (q <= k) { v = __expf(Sp[(size_t)q * W_ + k] - M2); l += v; }
        Sp[(size_t)q * W_ + k] = v;
    }
    red[ty][tx] = l;
    __syncthreads();

    if (ty == 0) {
        float L2 = 0.f;
#pragma unroll
        for (int i = 0; i < 8; i++) L2 += red[i][tx];
        g_inv[z * W_ + k] = 1.0f / (L2 * 32.0f);   // fold 1/sqrt(E)=1/32
    }
}

// ---------------------------------------------------------------------------
// Kernel 4: O[d,k] = inv[k] * sum_q V[d,q] * P[q,k]. 64x128 tile, BK=16, db.
// ---------------------------------------------------------------------------
__global__ __launch_bounds__(256, 2) void k_attnv()
{
    __shared__ float As[2][16][64];    // [buf][q][d]
    __shared__ float Bs[2][16][128];   // [buf][q][k]

    int z = blockIdx.y, b = z >> 4, h = z & 15;
    int n0 = blockIdx.x * 128;
    const float* V = g_qkv + (size_t)(8 + b) * E_ * W_ + (size_t)h * D_ * W_;
    const float* P = g_scores + (size_t)z * W_ * W_;
    float* O = g_attn_out + (size_t)b * E_ * W_ + (size_t)h * D_ * W_;

    const int tid = threadIdx.x;
    const int tx = tid & 15, ty = tid >> 4;

    const int vrow = tid >> 2;        // 0..63 (d)
    const int vcol = (tid & 3) * 4;   // 0..12 (q offset)
    const int prow = tid >> 4;        // 0..15 (q)
    const int pcol = (tid & 15) * 4;  // 0..60

    const float* Vp = V + (size_t)vrow * W_ + vcol;
    const float* Pp = P + (size_t)prow * W_ + n0 + pcol;

    float acc[4][8];
#pragma unroll
    for (int i = 0; i < 4; i++)
#pragma unroll
        for (int j = 0; j < 8; j++) acc[i][j] = 0.f;

    {
        float4 av = *(const float4*)(Vp);
        As[0][vcol + 0][vrow] = av.x;
        As[0][vcol + 1][vrow] = av.y;
        As[0][vcol + 2][vrow] = av.z;
        As[0][vcol + 3][vrow] = av.w;
        *(float4*)(&Bs[0][prow][pcol])      = *(const float4*)(Pp);
        *(float4*)(&Bs[0][prow][pcol + 64]) = *(const float4*)(Pp + 64);
    }
    __syncthreads();

    int buf = 0;
    const int qmax = n0 + 128;
    for (int kt = 16; kt <= qmax; kt += 16) {
        const bool has = (kt < qmax);
        float4 av = {0,0,0,0}, b0 = {0,0,0,0}, b1 = {0,0,0,0};
        if (has) {
            av = *(const float4*)(Vp + kt);
            b0 = *(const float4*)(Pp + (size_t)kt * W_);
            b1 = *(const float4*)(Pp + (size_t)kt * W_ + 64);
        }
#pragma unroll
        for (int kk = 0; kk < 16; kk++) {
            float4 a  = *(const float4*)(&As[buf][kk][ty * 4]);
            float4 B0 = *(const float4*)(&Bs[buf][kk][tx * 4]);
            float4 B1 = *(const float4*)(&Bs[buf][kk][64 + tx * 4]);
            float aa[4] = {a.x, a.y, a.z, a.w};
            float bb[8] = {B0.x, B0.y, B0.z, B0.w, B1.x, B1.y, B1.z, B1.w};
#pragma unroll
            for (int i = 0; i < 4; i++)
#pragma unroll
                for (int j = 0; j < 8; j++) acc[i][j] += aa[i] * bb[j];
        }
        if (has) {
            int nb = buf ^ 1;
            As[nb][vcol + 0][vrow] = av.x;
            As[nb][vcol + 1][vrow] = av.y;
            As[nb][vcol + 2][vrow] = av.z;
            As[nb][vcol + 3][vrow] = av.w;
            *(float4*)(&Bs[nb][prow][pcol])      = b0;
            *(float4*)(&Bs[nb][prow][pcol + 64]) = b1;
        }
        __syncthreads();
        buf ^= 1;
    }

    const float* invp = g_inv + z * W_ + n0;
#pragma unroll
    for (int jh = 0; jh < 2; jh++) {
        float4 iv = *(const float4*)(invp + jh * 64 + tx * 4);
#pragma unroll
        for (int i = 0; i < 4; i++) {
            int row = ty * 4 + i;
            float4 v;
            v.x = acc[i][jh * 4 + 0] * iv.x;
            v.y = acc[i][jh * 4 + 1] * iv.y;
            v.z = acc[i][jh * 4 + 2] * iv.z;
            v.w = acc[i][jh * 4 + 3] * iv.w;
            *(float4*)(&O[(size_t)row * W_ + n0 + jh * 64 + tx * 4]) = v;
        }
    }
}

// ---------------------------------------------------------------------------
// Kernel 5: y[b] = M @ O[b] + bias
// ---------------------------------------------------------------------------
__global__ __launch_bounds__(256, 2) void k_final(
    const float* __restrict__ Mw,
    const float* __restrict__ bias,
    float* __restrict__ out)
{
    int b = blockIdx.z;
    gemm_nn_db(Mw, E_, g_attn_out + (size_t)b * E_ * W_, W_,
               out + (size_t)b * E_ * W_, W_, E_, bias);
}

// ---------------------------------------------------------------------------
extern "C" void kernel_launch(void* const* d_in, const int* in_sizes, int n_in,
                              void* d_out, int out_size)
{
    const float* x  = (const float*)d_in[0];
    const float* LQ = (const float*)d_in[1];
    const float* LK = (const float*)d_in[2];
    const float* LV = (const float*)d_in[3];
    const float* Mw = (const float*)d_in[4];
    const float* bv = (const float*)d_in[5];
    float* out = (float*)d_out;

    dim3 blk(256);
    k_proj   <<<dim3(8, 8, 12), blk>>>(x, LQ, LK, LV);
    k_scores <<<dim3(8, 8, 64), blk>>>();
    k_softmax<<<dim3(32, 64),   blk>>>();
    k_attnv  <<<dim3(8, 64),    blk>>>();
    k_final  <<<dim3(8, 8, 4),  blk>>>(Mw, bv, out);
}

// round 3
// speedup vs baseline: 1.1365x; 1.0055x over previous
#include <cuda_runtime.h>
#include <math_constants.h>

#define E_ 1024
#define W_ 1024
#define B_ 4
#define H_ 16
#define D_ 64
#define BH_ 64   // B_*H_

typedef unsigned long long u64t;

// Scratch (allocation-free: __device__ globals)
__device__ float g_qkv[3ull * B_ * E_ * W_];        // [p][b][e][w]; p: 0=K, 1=Q, 2=V
__device__ float g_scores[(size_t)BH_ * W_ * W_];   // [bh][q][k]; unnormalized P after softmax
__device__ float g_attn_out[(size_t)B_ * E_ * W_];  // [b][e][w]
__device__ float g_inv[BH_ * W_];                   // per-column 1/(32*l)

// ---- packed fp32x2 helpers (Blackwell f32x2 pipe: 2 fp32 FMA per issue) ----
__device__ __forceinline__ u64t pack2(float x, float y) {
    u64t r; asm("mov.b64 %0, {%1,%2};" : "=l"(r) : "f"(x), "f"(y)); return r;
}
__device__ __forceinline__ u64t fma2(u64t a, u64t b, u64t c) {
    u64t d; asm("fma.rn.f32x2 %0, %1, %2, %3;" : "=l"(d) : "l"(a), "l"(b), "l"(c)); return d;
}
__device__ __forceinline__ float2 unpack2(u64t v) {
    float2 f; asm("mov.b64 {%0,%1}, %2;" : "=f"(f.x), "=f"(f.y) : "l"(v)); return f;
}

// ---------------------------------------------------------------------------
// 128x128 SGEMM body, NN, BK=16, double-buffered, 256 threads, 8x8 micro,
// FFMA2 inner loop (acc pairs along n).
// ---------------------------------------------------------------------------
__device__ __forceinline__ void gemm_nn_db(
    const float* __restrict__ A, int lda,
    const float* __restrict__ Bm, int ldb,
    float* __restrict__ C, int ldc,
    int Kdim, const float* __restrict__ bias)
{
    __shared__ float As[2][16][128];   // [buf][k][m]
    __shared__ float Bs[2][16][128];   // [buf][k][n]

    const int tid = threadIdx.x;
    const int tx  = tid & 15;
    const int ty  = tid >> 4;
    const int m0  = blockIdx.y * 128;
    const int n0  = blockIdx.x * 128;

    const int arow = tid >> 1;          // 0..127 (m)
    const int acol = (tid & 1) * 8;     // 0 or 8 (k offset)
    const int brow = tid >> 4;          // 0..15 (k)
    const int bcol = (tid & 15) * 4;    // 0..60 (n offset)

    const float* Ap = A  + (size_t)(m0 + arow) * lda + acol;
    const float* Bp = Bm + (size_t)brow * ldb + n0 + bcol;

    u64t acc[8][4];
#pragma unroll
    for (int i = 0; i < 8; i++)
#pragma unroll
        for (int j = 0; j < 4; j++) acc[i][j] = 0ull;

    {
        float4 a0 = *(const float4*)(Ap);
        float4 a1 = *(const float4*)(Ap + 4);
        float4 b0 = *(const float4*)(Bp);
        float4 b1 = *(const float4*)(Bp + 64);
        As[0][acol + 0][arow] = a0.x;
        As[0][acol + 1][arow] = a0.y;
        As[0][acol + 2][arow] = a0.z;
        As[0][acol + 3][arow] = a0.w;
        As[0][acol + 4][arow] = a1.x;
        As[0][acol + 5][arow] = a1.y;
        As[0][acol + 6][arow] = a1.z;
        As[0][acol + 7][arow] = a1.w;
        *(float4*)(&Bs[0][brow][bcol])      = b0;
        *(float4*)(&Bs[0][brow][bcol + 64]) = b1;
    }
    __syncthreads();

    int buf = 0;
    for (int kt = 16; kt <= Kdim; kt += 16) {
        const bool has = (kt < Kdim);
        float4 a0 = {0,0,0,0}, a1 = {0,0,0,0}, b0 = {0,0,0,0}, b1 = {0,0,0,0};
        if (has) {
            a0 = *(const float4*)(Ap + kt);
            a1 = *(const float4*)(Ap + kt + 4);
            b0 = *(const float4*)(Bp + (size_t)kt * ldb);
            b1 = *(const float4*)(Bp + (size_t)kt * ldb + 64);
        }
#pragma unroll
        for (int kk = 0; kk < 16; kk++) {
            float4 A0 = *(const float4*)(&As[buf][kk][ty * 4]);
            float4 A1 = *(const float4*)(&As[buf][kk][64 + ty * 4]);
            float4 B0 = *(const float4*)(&Bs[buf][kk][tx * 4]);
            float4 B1 = *(const float4*)(&Bs[buf][kk][64 + tx * 4]);
            u64t bp[4] = {pack2(B0.x, B0.y), pack2(B0.z, B0.w),
                          pack2(B1.x, B1.y), pack2(B1.z, B1.w)};
            float a[8] = {A0.x, A0.y, A0.z, A0.w, A1.x, A1.y, A1.z, A1.w};
#pragma unroll
            for (int i = 0; i < 8; i++) {
                u64t ai = pack2(a[i], a[i]);
#pragma unroll
                for (int j = 0; j < 4; j++) acc[i][j] = fma2(ai, bp[j], acc[i][j]);
            }
        }
        if (has) {
            int nb = buf ^ 1;
            As[nb][acol + 0][arow] = a0.x;
            As[nb][acol + 1][arow] = a0.y;
            As[nb][acol + 2][arow] = a0.z;
            As[nb][acol + 3][arow] = a0.w;
            As[nb][acol + 4][arow] = a1.x;
            As[nb][acol + 5][arow] = a1.y;
            As[nb][acol + 6][arow] = a1.z;
            As[nb][acol + 7][arow] = a1.w;
            *(float4*)(&Bs[nb][brow][bcol])      = b0;
            *(float4*)(&Bs[nb][brow][bcol + 64]) = b1;
        }
        __syncthreads();
        buf ^= 1;
    }

#pragma unroll
    for (int ih = 0; ih < 2; ih++)
#pragma unroll
        for (int i = 0; i < 4; i++) {
            int row = m0 + ih * 64 + ty * 4 + i;
            float bval = bias ? bias[row] : 0.f;
            int ii = ih * 4 + i;
#pragma unroll
            for (int jh = 0; jh < 2; jh++) {
                float2 p0 = unpack2(acc[ii][jh * 2 + 0]);
                float2 p1 = unpack2(acc[ii][jh * 2 + 1]);
                float4 v = {p0.x + bval, p0.y + bval, p1.x + bval, p1.y + bval};
                *(float4*)(&C[(size_t)row * ldc + n0 + jh * 64 + tx * 4]) = v;
            }
        }
}

// ---------------------------------------------------------------------------
// 128x128 SGEMM body, TN (both K-major), BK=16, double-buffered, FFMA2.
// ---------------------------------------------------------------------------
__device__ __forceinline__ void gemm_tn_db(
    const float* __restrict__ A, int lda,   // [Kdim][M]
    const float* __restrict__ Bm, int ldb,  // [Kdim][N]
    float* __restrict__ C, int ldc, int Kdim)
{
    __shared__ float As[2][16][128];
    __shared__ float Bs[2][16][128];

    const int tid = threadIdx.x;
    const int tx  = tid & 15;
    const int ty  = tid >> 4;
    const int m0  = blockIdx.y * 128;
    const int n0  = blockIdx.x * 128;

    const int row  = tid >> 4;          // 0..15 (k)
    const int col4 = (tid & 15) * 4;    // 0..60

    const float* Ap = A  + (size_t)row * lda + m0 + col4;
    const float* Bp = Bm + (size_t)row * ldb + n0 + col4;

    u64t acc[8][4];
#pragma unroll
    for (int i = 0; i < 8; i++)
#pragma unroll
        for (int j = 0; j < 4; j++) acc[i][j] = 0ull;

    {
        *(float4*)(&As[0][row][col4])      = *(const float4*)(Ap);
        *(float4*)(&As[0][row][col4 + 64]) = *(const float4*)(Ap + 64);
        *(float4*)(&Bs[0][row][col4])      = *(const float4*)(Bp);
        *(float4*)(&Bs[0][row][col4 + 64]) = *(const float4*)(Bp + 64);
    }
    __syncthreads();

    int buf = 0;
    for (int kt = 16; kt <= Kdim; kt += 16) {
        const bool has = (kt < Kdim);
        float4 a0 = {0,0,0,0}, a1 = {0,0,0,0}, b0 = {0,0,0,0}, b1 = {0,0,0,0};
        if (has) {
            a0 = *(const float4*)(Ap + (size_t)kt * lda);
            a1 = *(const float4*)(Ap + (size_t)kt * lda + 64);
            b0 = *(const float4*)(Bp + (size_t)kt * ldb);
            b1 = *(const float4*)(Bp + (size_t)kt * ldb + 64);
        }
#pragma unroll
        for (int kk = 0; kk < 16; kk++) {
            float4 A0 = *(const float4*)(&As[buf][kk][ty * 4]);
            float4 A1 = *(const float4*)(&As[buf][kk][64 + ty * 4]);
            float4 B0 = *(const float4*)(&Bs[buf][kk][tx * 4]);
            float4 B1 = *(const float4*)(&Bs[buf][kk][64 + tx * 4]);
            u64t bp[4] = {pack2(B0.x, B0.y), pack2(B0.z, B0.w),
                          pack2(B1.x, B1.y), pack2(B1.z, B1.w)};
            float a[8] = {A0.x, A0.y, A0.z, A0.w, A1.x, A1.y, A1.z, A1.w};
#pragma unroll
            for (int i = 0; i < 8; i++) {
                u64t ai = pack2(a[i], a[i]);
#pragma unroll
                for (int j = 0; j < 4; j++) acc[i][j] = fma2(ai, bp[j], acc[i][j]);
            }
        }
        if (has) {
            int nb = buf ^ 1;
            *(float4*)(&As[nb][row][col4])      = a0;
            *(float4*)(&As[nb][row][col4 + 64]) = a1;
            *(float4*)(&Bs[nb][row][col4])      = b0;
            *(float4*)(&Bs[nb][row][col4 + 64]) = b1;
        }
        __syncthreads();
        buf ^= 1;
    }

#pragma unroll
    for (int ih = 0; ih < 2; ih++)
#pragma unroll
        for (int i = 0; i < 4; i++) {
            int r = m0 + ih * 64 + ty * 4 + i;
            int ii = ih * 4 + i;
#pragma unroll
            for (int jh = 0; jh < 2; jh++) {
                float2 p0 = unpack2(acc[ii][jh * 2 + 0]);
                float2 p1 = unpack2(acc[ii][jh * 2 + 1]);
                float4 v = {p0.x, p0.y, p1.x, p1.y};
                *(float4*)(&C[(size_t)r * ldc + n0 + jh * 64 + tx * 4]) = v;
            }
        }
}

// ---------------------------------------------------------------------------
// Kernel 1: projections. z = p*4 + b; g_qkv[p][b] = L_p @ x[p][b]
// ---------------------------------------------------------------------------
__global__ __launch_bounds__(256, 2) void k_proj(
    const float* __restrict__ x,
    const float* __restrict__ LQ,
    const float* __restrict__ LK,
    const float* __restrict__ LV)
{
    int z = blockIdx.z;
    int p = z >> 2;
    const float* A  = (p == 0) ? LK : (p == 1) ? LQ : LV;
    const float* Bm = x + (size_t)z * E_ * W_;
    float*       C  = g_qkv + (size_t)z * E_ * W_;
    gemm_nn_db(A, E_, Bm, W_, C, W_, E_, nullptr);
}

// ---------------------------------------------------------------------------
// Kernel 2: scores. S[bh][q][k] = sum_d Q[d,q] * K[d,k]. Skip fully-masked tiles.
// ---------------------------------------------------------------------------
__global__ __launch_bounds__(256, 2) void k_scores()
{
    int z = blockIdx.z;            // bh
    int m0 = blockIdx.y * 128;     // q tile
    int n0 = blockIdx.x * 128;     // k tile
    if (m0 > n0 + 127) return;     // fully masked tile
    int b = z >> 4, h = z & 15;
    const float* Aq = g_qkv + (size_t)(4 + b) * E_ * W_ + (size_t)h * D_ * W_; // Q
    const float* Bk = g_qkv + (size_t)(0 + b) * E_ * W_ + (size_t)h * D_ * W_; // K
    float* Sp = g_scores + (size_t)z * W_ * W_;
    gemm_tn_db(Aq, W_, Bk, W_, Sp, W_, D_);
}

// ---------------------------------------------------------------------------
// Kernel 3: column softmax over q (axis=-2), causal q<=k. Two passes:
//  pass1 max, pass2 exp+sum, store UNNORMALIZED P (0 for q>k),
//  per-column 1/(32*l) into g_inv (applied in k_attnv epilogue).
// ---------------------------------------------------------------------------
__global__ __launch_bounds__(256) void k_softmax()
{
    int z  = blockIdx.y;
    int k0 = blockIdx.x * 32;
    int tx = threadIdx.x & 31;
    int ty = threadIdx.x >> 5;
    int k  = k0 + tx;
    float* Sp = g_scores + (size_t)z * W_ * W_;

    __shared__ float red[8][32];

    float m = -CUDART_INF_F;
    for (int q = ty; q <= k; q += 8)
        m = fmaxf(m, Sp[(size_t)q * W_ + k]);
    red[ty][tx] = m;
    __syncthreads();

    float M2 = red[0][tx];
#pragma unroll
    for (int i = 1; i < 8; i++) M2 = fmaxf(M2, red[i][tx]);
    __syncthreads();

    float l = 0.f;
    for (int q = ty; q < W_; q += 8) {
        float v = 0.f;
        if (q <= k) { v = __expf(Sp[(size_t)q * W_ + k] - M2); l += v; }
        Sp[(size_t)q * W_ + k] = v;
    }
    red[ty][tx] = l;
    __syncthreads();

    if (ty == 0) {
        float L2 = 0.f;
#pragma unroll
        for (int i = 0; i < 8; i++) L2 += red[i][tx];
        g_inv[z * W_ + k] = 1.0f / (L2 * 32.0f);   // fold 1/sqrt(E)=1/32
    }
}

// ---------------------------------------------------------------------------
// Kernel 4: O[d,k] = inv[k] * sum_q V[d,q] * P[q,k]. 64x128 tile, BK=16, FFMA2.
// ---------------------------------------------------------------------------
__global__ __launch_bounds__(256, 2) void k_attnv()
{
    __shared__ float As[2][16][64];    // [buf][q][d]
    __shared__ float Bs[2][16][128];   // [buf][q][k]

    int z = blockIdx.y, b = z >> 4, h = z & 15;
    int n0 = blockIdx.x * 128;
    const float* V = g_qkv + (size_t)(8 + b) * E_ * W_ + (size_t)h * D_ * W_;
    const float* P = g_scores + (size_t)z * W_ * W_;
    float* O = g_attn_out + (size_t)b * E_ * W_ + (size_t)h * D_ * W_;

    const int tid = threadIdx.x;
    const int tx = tid & 15, ty = tid >> 4;

    const int vrow = tid >> 2;        // 0..63 (d)
    const int vcol = (tid & 3) * 4;   // 0..12 (q offset)
    const int prow = tid >> 4;        // 0..15 (q)
    const int pcol = (tid & 15) * 4;  // 0..60

    const float* Vp = V + (size_t)vrow * W_ + vcol;
    const float* Pp = P + (size_t)prow * W_ + n0 + pcol;

    u64t acc[4][4];
#pragma unroll
    for (int i = 0; i < 4; i++)
#pragma unroll
        for (int j = 0; j < 4; j++) acc[i][j] = 0ull;

    {
        float4 av = *(const float4*)(Vp);
        As[0][vcol + 0][vrow] = av.x;
        As[0][vcol + 1][vrow] = av.y;
        As[0][vcol + 2][vrow] = av.z;
        As[0][vcol + 3][vrow] = av.w;
        *(float4*)(&Bs[0][prow][pcol])      = *(const float4*)(Pp);
        *(float4*)(&Bs[0][prow][pcol + 64]) = *(const float4*)(Pp + 64);
    }
    __syncthreads();

    int buf = 0;
    const int qmax = n0 + 128;
    for (int kt = 16; kt <= qmax; kt += 16) {
        const bool has = (kt < qmax);
        float4 av = {0,0,0,0}, b0 = {0,0,0,0}, b1 = {0,0,0,0};
        if (has) {
            av = *(const float4*)(Vp + kt);
            b0 = *(const float4*)(Pp + (size_t)kt * W_);
            b1 = *(const float4*)(Pp + (size_t)kt * W_ + 64);
        }
#pragma unroll
        for (int kk = 0; kk < 16; kk++) {
            float4 a  = *(const float4*)(&As[buf][kk][ty * 4]);
            float4 B0 = *(const float4*)(&Bs[buf][kk][tx * 4]);
            float4 B1 = *(const float4*)(&Bs[buf][kk][64 + tx * 4]);
            u64t bp[4] = {pack2(B0.x, B0.y), pack2(B0.z, B0.w),
                          pack2(B1.x, B1.y), pack2(B1.z, B1.w)};
            float aa[4] = {a.x, a.y, a.z, a.w};
#pragma unroll
            for (int i = 0; i < 4; i++) {
                u64t ai = pack2(aa[i], aa[i]);
#pragma unroll
                for (int j = 0; j < 4; j++) acc[i][j] = fma2(ai, bp[j], acc[i][j]);
            }
        }
        if (has) {
            int nb = buf ^ 1;
            As[nb][vcol + 0][vrow] = av.x;
            As[nb][vcol + 1][vrow] = av.y;
            As[nb][vcol + 2][vrow] = av.z;
            As[nb][vcol + 3][vrow] = av.w;
            *(float4*)(&Bs[nb][prow][pcol])      = b0;
            *(float4*)(&Bs[nb][prow][pcol + 64]) = b1;
        }
        __syncthreads();
        buf ^= 1;
    }

    const float* invp = g_inv + z * W_ + n0;
#pragma unroll
    for (int jh = 0; jh < 2; jh++) {
        float4 iv = *(const float4*)(invp + jh * 64 + tx * 4);
#pragma unroll
        for (int i = 0; i < 4; i++) {
            int row = ty * 4 + i;
            float2 p0 = unpack2(acc[i][jh * 2 + 0]);
            float2 p1 = unpack2(acc[i][jh * 2 + 1]);
            float4 v = {p0.x * iv.x, p0.y * iv.y, p1.x * iv.z, p1.y * iv.w};
            *(float4*)(&O[(size_t)row * W_ + n0 + jh * 64 + tx * 4]) = v;
        }
    }
}

// ---------------------------------------------------------------------------
// Kernel 5: y[b] = M @ O[b] + bias
// ---------------------------------------------------------------------------
__global__ __launch_bounds__(256, 2) void k_final(
    const float* __restrict__ Mw,
    const float* __restrict__ bias,
    float* __restrict__ out)
{
    int b = blockIdx.z;
    gemm_nn_db(Mw, E_, g_attn_out + (size_t)b * E_ * W_, W_,
               out + (size_t)b * E_ * W_, W_, E_, bias);
}

// ---------------------------------------------------------------------------
extern "C" void kernel_launch(void* const* d_in, const int* in_sizes, int n_in,
                              void* d_out, int out_size)
{
    const float* x  = (const float*)d_in[0];
    const float* LQ = (const float*)d_in[1];
    const float* LK = (const float*)d_in[2];
    const float* LV = (const float*)d_in[3];
    const float* Mw = (const float*)d_in[4];
    const float* bv = (const float*)d_in[5];
    float* out = (float*)d_out;

    dim3 blk(256);
    k_proj   <<<dim3(8, 8, 12), blk>>>(x, LQ, LK, LV);
    k_scores <<<dim3(8, 8, 64), blk>>>();
    k_softmax<<<dim3(32, 64),   blk>>>();
    k_attnv  <<<dim3(8, 64),    blk>>>();
    k_final  <<<dim3(8, 8, 4),  blk>>>(Mw, bv, out);
}

// round 7
// speedup vs baseline: 1.3159x; 1.1579x over previous
#include <cuda_runtime.h>
#include <cuda_bf16.h>
#include <mma.h>
#include <math_constants.h>

using namespace nvcuda;

#define E_ 1024
#define W_ 1024
#define B_ 4
#define H_ 16
#define D_ 64
#define BH_ 64

typedef unsigned long long u64t;
typedef unsigned int u32t;

// ---------------- scratch (allocation-free) ----------------
__device__ float g_qkv[3ull * B_ * E_ * W_];        // [p][b][e][w]
__device__ float g_scores[(size_t)BH_ * W_ * W_];   // [bh][q][k]
__device__ float g_attn_out[(size_t)B_ * E_ * W_];  // [b][e][w]
__device__ float g_inv[BH_ * W_];
__device__ __nv_bfloat16 g_w_hi[4ull * E_ * E_];    // [p: K,Q,V,M][e][f]
__device__ __nv_bfloat16 g_w_lo[4ull * E_ * E_];
__device__ __nv_bfloat16 g_x_hi[12ull * E_ * W_];   // [z][e][w]
__device__ __nv_bfloat16 g_x_lo[12ull * E_ * W_];
__device__ __nv_bfloat16 g_o_hi[4ull * E_ * W_];
__device__ __nv_bfloat16 g_o_lo[4ull * E_ * W_];

// ---------------- fp32 -> bf16 hi/lo split helpers ----------------
__device__ __forceinline__ void split4(float4 v, uint2& uh, uint2& ul)
{
    __nv_bfloat16 h0 = __float2bfloat16_rn(v.x);
    __nv_bfloat16 h1 = __float2bfloat16_rn(v.y);
    __nv_bfloat16 h2 = __float2bfloat16_rn(v.z);
    __nv_bfloat16 h3 = __float2bfloat16_rn(v.w);
    __nv_bfloat16 l0 = __float2bfloat16_rn(v.x - __bfloat162float(h0));
    __nv_bfloat16 l1 = __float2bfloat16_rn(v.y - __bfloat162float(h1));
    __nv_bfloat16 l2 = __float2bfloat16_rn(v.z - __bfloat162float(h2));
    __nv_bfloat16 l3 = __float2bfloat16_rn(v.w - __bfloat162float(h3));
    uh.x = (u32t)__bfloat16_as_ushort(h0) | ((u32t)__bfloat16_as_ushort(h1) << 16);
    uh.y = (u32t)__bfloat16_as_ushort(h2) | ((u32t)__bfloat16_as_ushort(h3) << 16);
    ul.x = (u32t)__bfloat16_as_ushort(l0) | ((u32t)__bfloat16_as_ushort(l1) << 16);
    ul.y = (u32t)__bfloat16_as_ushort(l2) | ((u32t)__bfloat16_as_ushort(l3) << 16);
}

// weights: src harness ptr -> g_w_hi/lo slot p  (device globals referenced in device code)
__global__ __launch_bounds__(256) void k_split_w(const float* __restrict__ s, int p)
{
    size_t i = ((size_t)blockIdx.x * 256 + threadIdx.x) * 4;
    uint2 uh, ul;
    split4(*(const float4*)(s + i), uh, ul);
    size_t o = (size_t)p * E_ * E_ + i;
    *(uint2*)(g_w_hi + o) = uh;
    *(uint2*)(g_w_lo + o) = ul;
}

// x: harness ptr -> g_x_hi/lo
__global__ __launch_bounds__(256) void k_split_x(const float* __restrict__ s)
{
    size_t i = ((size_t)blockIdx.x * 256 + threadIdx.x) * 4;
    uint2 uh, ul;
    split4(*(const float4*)(s + i), uh, ul);
    *(uint2*)(g_x_hi + i) = uh;
    *(uint2*)(g_x_lo + i) = ul;
}

// attn_out (device global) -> g_o_hi/lo
__global__ __launch_bounds__(256) void k_split_o()
{
    size_t i = ((size_t)blockIdx.x * 256 + threadIdx.x) * 4;
    uint2 uh, ul;
    split4(*(const float4*)(g_attn_out + i), uh, ul);
    *(uint2*)(g_o_hi + i) = uh;
    *(uint2*)(g_o_lo + i) = ul;
}

// ---------------- wmma bf16 3-term GEMM ----------------
// C[128x128 tile] = Ah*Bh + Ah*Bl + Al*Bh (fp32 accum). A [M][K], B [K][N] bf16.
#define AK 40
#define BN 136
#define A_BUF 5120            // elems per A buffer (128*40)
#define B_BUF 4352            // elems per B buffer (32*136)
#define OFF_AL_B 20480        // byte offsets
#define OFF_BH_B 40960
#define OFF_BL_B 58368
#define SMEM_MMA 75776

typedef wmma::fragment<wmma::matrix_a, 16, 16, 16, __nv_bfloat16, wmma::row_major> FragA;
typedef wmma::fragment<wmma::matrix_b, 16, 16, 16, __nv_bfloat16, wmma::row_major> FragB;
typedef wmma::fragment<wmma::accumulator, 16, 16, 16, float> FragC;

__device__ __forceinline__ void mma_gemm_body(
    const __nv_bfloat16* __restrict__ Ah, const __nv_bfloat16* __restrict__ Al,
    const __nv_bfloat16* __restrict__ Bh, const __nv_bfloat16* __restrict__ Bl,
    float* __restrict__ C, const float* __restrict__ bias)
{
    extern __shared__ __align__(128) char smem[];
    __nv_bfloat16* sAh = (__nv_bfloat16*)(smem);
    __nv_bfloat16* sAl = (__nv_bfloat16*)(smem + OFF_AL_B);
    __nv_bfloat16* sBh = (__nv_bfloat16*)(smem + OFF_BH_B);
    __nv_bfloat16* sBl = (__nv_bfloat16*)(smem + OFF_BL_B);
    float* stage = (float*)smem;            // [128][132] fp32, reused after compute

    const int tid = threadIdx.x;
    const int w = tid >> 5;
    const int wm = w & 3;                   // 4 warps along m
    const int wn = w >> 2;                  // 2 warps along n
    const int m0 = blockIdx.y * 128;
    const int n0 = blockIdx.x * 128;

    const int ar = tid >> 1, ak = (tid & 1) * 16;   // A: 128 rows x 32 k
    const int bk = tid >> 3, bn = (tid & 7) * 16;   // B: 32 k x 128 n

    const __nv_bfloat16* gAh = Ah + (size_t)(m0 + ar) * 1024 + ak;
    const __nv_bfloat16* gAl = Al + (size_t)(m0 + ar) * 1024 + ak;
    const __nv_bfloat16* gBh = Bh + (size_t)bk * 1024 + n0 + bn;
    const __nv_bfloat16* gBl = Bl + (size_t)bk * 1024 + n0 + bn;

    FragC acc[2][4];
#pragma unroll
    for (int mi = 0; mi < 2; mi++)
#pragma unroll
        for (int ni = 0; ni < 4; ni++) wmma::fill_fragment(acc[mi][ni], 0.0f);

    // preload stage 0
    {
        uint4 ah0 = *(const uint4*)(gAh), ah1 = *(const uint4*)(gAh + 8);
        uint4 al0 = *(const uint4*)(gAl), al1 = *(const uint4*)(gAl + 8);
        uint4 bh0 = *(const uint4*)(gBh), bh1 = *(const uint4*)(gBh + 8);
        uint4 bl0 = *(const uint4*)(gBl), bl1 = *(const uint4*)(gBl + 8);
        *(uint4*)(&sAh[ar * AK + ak])     = ah0;
        *(uint4*)(&sAh[ar * AK + ak + 8]) = ah1;
        *(uint4*)(&sAl[ar * AK + ak])     = al0;
        *(uint4*)(&sAl[ar * AK + ak + 8]) = al1;
        *(uint4*)(&sBh[bk * BN + bn])     = bh0;
        *(uint4*)(&sBh[bk * BN + bn + 8]) = bh1;
        *(uint4*)(&sBl[bk * BN + bn])     = bl0;
        *(uint4*)(&sBl[bk * BN + bn + 8]) = bl1;
    }
    __syncthreads();

    int buf = 0;
    for (int kt = 32; kt <= 1024; kt += 32) {
        const bool has = (kt < 1024);
        uint4 ah0, ah1, al0, al1, bh0, bh1, bl0, bl1;
        if (has) {
            ah0 = *(const uint4*)(gAh + kt);
            ah1 = *(const uint4*)(gAh + kt + 8);
            al0 = *(const uint4*)(gAl + kt);
            al1 = *(const uint4*)(gAl + kt + 8);
            bh0 = *(const uint4*)(gBh + (size_t)kt * 1024);
            bh1 = *(const uint4*)(gBh + (size_t)kt * 1024 + 8);
            bl0 = *(const uint4*)(gBl + (size_t)kt * 1024);
            bl1 = *(const uint4*)(gBl + (size_t)kt * 1024 + 8);
        }

        const int ab = buf * A_BUF, bb = buf * B_BUF;
#pragma unroll
        for (int kk = 0; kk < 32; kk += 16) {
            FragA fah[2], fal[2];
#pragma unroll
            for (int mi = 0; mi < 2; mi++) {
                wmma::load_matrix_sync(fah[mi], &sAh[ab + (wm * 32 + mi * 16) * AK + kk], AK);
                wmma::load_matrix_sync(fal[mi], &sAl[ab + (wm * 32 + mi * 16) * AK + kk], AK);
            }
#pragma unroll
            for (int ni = 0; ni < 4; ni++) {
                FragB fbh, fbl;
                wmma::load_matrix_sync(fbh, &sBh[bb + kk * BN + wn * 64 + ni * 16], BN);
                wmma::load_matrix_sync(fbl, &sBl[bb + kk * BN + wn * 64 + ni * 16], BN);
#pragma unroll
                for (int mi = 0; mi < 2; mi++) {
                    wmma::mma_sync(acc[mi][ni], fah[mi], fbh, acc[mi][ni]);
                    wmma::mma_sync(acc[mi][ni], fah[mi], fbl, acc[mi][ni]);
                    wmma::mma_sync(acc[mi][ni], fal[mi], fbh, acc[mi][ni]);
                }
            }
        }

        if (has) {
            const int nb = buf ^ 1;
            const int nab = nb * A_BUF, nbb = nb * B_BUF;
            *(uint4*)(&sAh[nab + ar * AK + ak])     = ah0;
            *(uint4*)(&sAh[nab + ar * AK + ak + 8]) = ah1;
            *(uint4*)(&sAl[nab + ar * AK + ak])     = al0;
            *(uint4*)(&sAl[nab + ar * AK + ak + 8]) = al1;
            *(uint4*)(&sBh[nbb + bk * BN + bn])     = bh0;
            *(uint4*)(&sBh[nbb + bk * BN + bn + 8]) = bh1;
            *(uint4*)(&sBl[nbb + bk * BN + bn])     = bl0;
            *(uint4*)(&sBl[nbb + bk * BN + bn + 8]) = bl1;
        }
        __syncthreads();
        buf ^= 1;
    }

    // epilogue: stage in smem, then bias + vector store
#pragma unroll
    for (int mi = 0; mi < 2; mi++)
#pragma unroll
        for (int ni = 0; ni < 4; ni++)
            wmma::store_matrix_sync(&stage[(wm * 32 + mi * 16) * 132 + wn * 64 + ni * 16],
                                    acc[mi][ni], 132, wmma::mem_row_major);
    __syncthreads();

    {
        const int r = tid >> 1;
        const int hf = (tid & 1) * 64;
        const float bv = bias ? bias[m0 + r] : 0.f;
        float* dst = C + (size_t)(m0 + r) * 1024 + n0 + hf;
        const float* src = stage + r * 132 + hf;
#pragma unroll
        for (int j = 0; j < 16; j++) {
            float4 v = *(const float4*)(src + j * 4);
            v.x += bv; v.y += bv; v.z += bv; v.w += bv;
            *(float4*)(dst + j * 4) = v;
        }
    }
}

__global__ __launch_bounds__(256) void k_proj_mma()
{
    int z = blockIdx.z;
    int p = z >> 2;   // 0=K,1=Q,2=V
    // all scratch pointers computed in DEVICE code
    mma_gemm_body(g_w_hi + (size_t)p * E_ * E_, g_w_lo + (size_t)p * E_ * E_,
                  g_x_hi + (size_t)z * E_ * W_, g_x_lo + (size_t)z * E_ * W_,
                  g_qkv + (size_t)z * E_ * W_, nullptr);
}

__global__ __launch_bounds__(256) void k_final_mma(
    const float* __restrict__ bias, float* __restrict__ out)
{
    int b = blockIdx.z;
    mma_gemm_body(g_w_hi + 3ull * E_ * E_, g_w_lo + 3ull * E_ * E_,
                  g_o_hi + (size_t)b * E_ * W_, g_o_lo + (size_t)b * E_ * W_,
                  out + (size_t)b * E_ * W_, bias);
}

// ---------------- packed fp32x2 helpers ----------------
__device__ __forceinline__ u64t pack2(float x, float y) {
    u64t r; asm("mov.b64 %0, {%1,%2};" : "=l"(r) : "f"(x), "f"(y)); return r;
}
__device__ __forceinline__ u64t fma2(u64t a, u64t b, u64t c) {
    u64t d; asm("fma.rn.f32x2 %0, %1, %2, %3;" : "=l"(d) : "l"(a), "l"(b), "l"(c)); return d;
}
__device__ __forceinline__ float2 unpack2(u64t v) {
    float2 f; asm("mov.b64 {%0,%1}, %2;" : "=f"(f.x), "=f"(f.y) : "l"(v)); return f;
}

// ---------------- scores: S[bh][q][k] = sum_d Q[d,q] K[d,k] ----------------
__global__ __launch_bounds__(256, 2) void k_scores()
{
    __shared__ float As[2][16][128];
    __shared__ float Bs[2][16][128];

    int z = blockIdx.z;
    int m0 = blockIdx.y * 128;
    int n0 = blockIdx.x * 128;
    if (m0 > n0 + 127) return;
    int b = z >> 4, h = z & 15;
    const float* A  = g_qkv + (size_t)(4 + b) * E_ * W_ + (size_t)h * D_ * W_;
    const float* Bm = g_qkv + (size_t)(0 + b) * E_ * W_ + (size_t)h * D_ * W_;
    float* C = g_scores + (size_t)z * W_ * W_;

    const int tid = threadIdx.x;
    const int tx = tid & 15, ty = tid >> 4;
    const int row = tid >> 4, col4 = (tid & 15) * 4;
    const float* Ap = A  + (size_t)row * W_ + m0 + col4;
    const float* Bp = Bm + (size_t)row * W_ + n0 + col4;

    u64t acc[8][4];
#pragma unroll
    for (int i = 0; i < 8; i++)
#pragma unroll
        for (int j = 0; j < 4; j++) acc[i][j] = 0ull;

    *(float4*)(&As[0][row][col4])      = *(const float4*)(Ap);
    *(float4*)(&As[0][row][col4 + 64]) = *(const float4*)(Ap + 64);
    *(float4*)(&Bs[0][row][col4])      = *(const float4*)(Bp);
    *(float4*)(&Bs[0][row][col4 + 64]) = *(const float4*)(Bp + 64);
    __syncthreads();

    int buf = 0;
    for (int kt = 16; kt <= D_; kt += 16) {
        const bool has = (kt < D_);
        float4 a0 = {0,0,0,0}, a1 = {0,0,0,0}, b0 = {0,0,0,0}, b1 = {0,0,0,0};
        if (has) {
            a0 = *(const float4*)(Ap + (size_t)kt * W_);
            a1 = *(const float4*)(Ap + (size_t)kt * W_ + 64);
            b0 = *(const float4*)(Bp + (size_t)kt * W_);
            b1 = *(const float4*)(Bp + (size_t)kt * W_ + 64);
        }
#pragma unroll
        for (int kk = 0; kk < 16; kk++) {
            float4 A0 = *(const float4*)(&As[buf][kk][ty * 4]);
            float4 A1 = *(const float4*)(&As[buf][kk][64 + ty * 4]);
            float4 B0 = *(const float4*)(&Bs[buf][kk][tx * 4]);
            float4 B1 = *(const float4*)(&Bs[buf][kk][64 + tx * 4]);
            u64t bp[4] = {pack2(B0.x, B0.y), pack2(B0.z, B0.w), pack2(B1.x, B1.y), pack2(B1.z, B1.w)};
            float a[8] = {A0.x, A0.y, A0.z, A0.w, A1.x, A1.y, A1.z, A1.w};
#pragma unroll
            for (int i = 0; i < 8; i++) {
                u64t ai = pack2(a[i], a[i]);
#pragma unroll
                for (int j = 0; j < 4; j++) acc[i][j] = fma2(ai, bp[j], acc[i][j]);
            }
        }
        if (has) {
            int nb = buf ^ 1;
            *(float4*)(&As[nb][row][col4])      = a0;
            *(float4*)(&As[nb][row][col4 + 64]) = a1;
            *(float4*)(&Bs[nb][row][col4])      = b0;
            *(float4*)(&Bs[nb][row][col4 + 64]) = b1;
        }
        __syncthreads();
        buf ^= 1;
    }

#pragma unroll
    for (int ih = 0; ih < 2; ih++)
#pragma unroll
        for (int i = 0; i < 4; i++) {
            int r = m0 + ih * 64 + ty * 4 + i;
            int ii = ih * 4 + i;
#pragma unroll
            for (int jh = 0; jh < 2; jh++) {
                float2 p0 = unpack2(acc[ii][jh * 2 + 0]);
                float2 p1 = unpack2(acc[ii][jh * 2 + 1]);
                float4 v = {p0.x, p0.y, p1.x, p1.y};
                *(float4*)(&C[(size_t)r * W_ + n0 + jh * 64 + tx * 4]) = v;
            }
        }
}

// ---------------- softmax over q (axis=-2), causal ----------------
__global__ __launch_bounds__(256) void k_softmax()
{
    int z  = blockIdx.y;
    int k0 = blockIdx.x * 32;
    int tx = threadIdx.x & 31;
    int ty = threadIdx.x >> 5;
    int k  = k0 + tx;
    float* Sp = g_scores + (size_t)z * W_ * W_;

    __shared__ float red[8][32];

    float m = -CUDART_INF_F;
    for (int q = ty; q <= k; q += 8)
        m = fmaxf(m, Sp[(size_t)q * W_ + k]);
    red[ty][tx] = m;
    __syncthreads();

    float M2 = red[0][tx];
#pragma unroll
    for (int i = 1; i < 8; i++) M2 = fmaxf(M2, red[i][tx]);
    __syncthreads();

    float l = 0.f;
    for (int q = ty; q < W_; q += 8) {
        float v = 0.f;
        if (q <= k) { v = __expf(Sp[(size_t)q * W_ + k] - M2); l += v; }
        Sp[(size_t)q * W_ + k] = v;
    }
    red[ty][tx] = l;
    __syncthreads();

    if (ty == 0) {
        float L2 = 0.f;
#pragma unroll
        for (int i = 0; i < 8; i++) L2 += red[i][tx];
        g_inv[z * W_ + k] = 1.0f / (L2 * 32.0f);
    }
}

// ---------------- attnv: O[d,k] = inv[k] * sum_q V[d,q] P[q,k] ----------------
__global__ __launch_bounds__(256, 2) void k_attnv()
{
    __shared__ float As[2][16][64];
    __shared__ float Bs[2][16][128];

    int z = blockIdx.y, b = z >> 4, h = z & 15;
    int n0 = blockIdx.x * 128;
    const float* V = g_qkv + (size_t)(8 + b) * E_ * W_ + (size_t)h * D_ * W_;
    const float* P = g_scores + (size_t)z * W_ * W_;
    float* O = g_attn_out + (size_t)b * E_ * W_ + (size_t)h * D_ * W_;

    const int tid = threadIdx.x;
    const int tx = tid & 15, ty = tid >> 4;
    const int vrow = tid >> 2, vcol = (tid & 3) * 4;
    const int prow = tid >> 4, pcol = (tid & 15) * 4;
    const float* Vp = V + (size_t)vrow * W_ + vcol;
    const float* Pp = P + (size_t)prow * W_ + n0 + pcol;

    u64t acc[4][4];
#pragma unroll
    for (int i = 0; i < 4; i++)
#pragma unroll
        for (int j = 0; j < 4; j++) acc[i][j] = 0ull;

    {
        float4 av = *(const float4*)(Vp);
        As[0][vcol + 0][vrow] = av.x;
        As[0][vcol + 1][vrow] = av.y;
        As[0][vcol + 2][vrow] = av.z;
        As[0][vcol + 3][vrow] = av.w;
        *(float4*)(&Bs[0][prow][pcol])      = *(const float4*)(Pp);
        *(float4*)(&Bs[0][prow][pcol + 64]) = *(const float4*)(Pp + 64);
    }
    __syncthreads();

    int buf = 0;
    const int qmax = n0 + 128;
    for (int kt = 16; kt <= qmax; kt += 16) {
        const bool has = (kt < qmax);
        float4 av = {0,0,0,0}, b0 = {0,0,0,0}, b1 = {0,0,0,0};
        if (has) {
            av = *(const float4*)(Vp + kt);
            b0 = *(const float4*)(Pp + (size_t)kt * W_);
            b1 = *(const float4*)(Pp + (size_t)kt * W_ + 64);
        }
#pragma unroll
        for (int kk = 0; kk < 16; kk++) {
            float4 a  = *(const float4*)(&As[buf][kk][ty * 4]);
            float4 B0 = *(const float4*)(&Bs[buf][kk][tx * 4]);
            float4 B1 = *(const float4*)(&Bs[buf][kk][64 + tx * 4]);
            u64t bp[4] = {pack2(B0.x, B0.y), pack2(B0.z, B0.w), pack2(B1.x, B1.y), pack2(B1.z, B1.w)};
            float aa[4] = {a.x, a.y, a.z, a.w};
#pragma unroll
            for (int i = 0; i < 4; i++) {
                u64t ai = pack2(aa[i], aa[i]);
#pragma unroll
                for (int j = 0; j < 4; j++) acc[i][j] = fma2(ai, bp[j], acc[i][j]);
            }
        }
        if (has) {
            int nb = buf ^ 1;
            As[nb][vcol + 0][vrow] = av.x;
            As[nb][vcol + 1][vrow] = av.y;
            As[nb][vcol + 2][vrow] = av.z;
            As[nb][vcol + 3][vrow] = av.w;
            *(float4*)(&Bs[nb][prow][pcol])      = b0;
            *(float4*)(&Bs[nb][prow][pcol + 64]) = b1;
        }
        __syncthreads();
        buf ^= 1;
    }

    const float* invp = g_inv + z * W_ + n0;
#pragma unroll
    for (int jh = 0; jh < 2; jh++) {
        float4 iv = *(const float4*)(invp + jh * 64 + tx * 4);
#pragma unroll
        for (int i = 0; i < 4; i++) {
            int row = ty * 4 + i;
            float2 p0 = unpack2(acc[i][jh * 2 + 0]);
            float2 p1 = unpack2(acc[i][jh * 2 + 1]);
            float4 v = {p0.x * iv.x, p0.y * iv.y, p1.x * iv.z, p1.y * iv.w};
            *(float4*)(&O[(size_t)row * W_ + n0 + jh * 64 + tx * 4]) = v;
        }
    }
}

// ---------------------------------------------------------------------------
extern "C" void kernel_launch(void* const* d_in, const int* in_sizes, int n_in,
                              void* d_out, int out_size)
{
    const float* x  = (const float*)d_in[0];
    const float* LQ = (const float*)d_in[1];
    const float* LK = (const float*)d_in[2];
    const float* LV = (const float*)d_in[3];
    const float* Mw = (const float*)d_in[4];
    const float* bv = (const float*)d_in[5];
    float* out = (float*)d_out;

    cudaFuncSetAttribute(k_proj_mma,  cudaFuncAttributeMaxDynamicSharedMemorySize, SMEM_MMA);
    cudaFuncSetAttribute(k_final_mma, cudaFuncAttributeMaxDynamicSharedMemorySize, SMEM_MMA);

    dim3 blk(256);

    // splits: harness pointers in, device-global destinations selected in device code
    k_split_w<<<1024, blk>>>(LK, 0);
    k_split_w<<<1024, blk>>>(LQ, 1);
    k_split_w<<<1024, blk>>>(LV, 2);
    k_split_w<<<1024, blk>>>(Mw, 3);
    k_split_x<<<12288, blk>>>(x);

    k_proj_mma<<<dim3(8, 8, 12), blk, SMEM_MMA>>>();
    k_scores  <<<dim3(8, 8, 64), blk>>>();
    k_softmax <<<dim3(32, 64),   blk>>>();
    k_attnv   <<<dim3(8, 64),    blk>>>();

    k_split_o<<<4096, blk>>>();
    k_final_mma<<<dim3(8, 8, 4), blk, SMEM_MMA>>>(bv, out);
}